// round 15
// baseline (speedup 1.0000x reference)
#include <cuda_runtime.h>
#include <cuda_fp16.h>
#include <math.h>
#include <stdint.h>

#define NN    50000
#define DD    128
#define EADJ  800000
#define EPRED 500000
#define BNEPS 1e-5f
#define SCANB 196          // ceil(NN/256)
#define NCOPY 32           // stat partial copies
#define SH    136          // smem half-stride per row (u32 stride 68)
#define TILES 391          // ceil(NN/128)
#define GEMC  148          // persistent CTAs (1/SM)

// ---------------- scratch ----------------------------------------------------
__device__ __half  g_ah[NN * DD];              // fp16 pre-converted A
__device__ __half2 g_supp_h[NN * (DD / 2)];    // fp16 support
__device__ float g_tmp[NN * DD];               // layer-1 pre-BN output
__device__ float g_tmp2[NN * DD];              // layer-2 pre-BN output
__device__ float g_statpart[2 * NCOPY * 2 * DD];
__device__ float g_bnab[2 * 2 * DD];           // [layer][a(128) | b(128)]
__device__ float g_s1[NN];
__device__ float g_s2[NN];
__device__ int   g_counts[NN];
__device__ int   g_rowstart[NN + 1];
__device__ int   g_cursor[NN];
__device__ int   g_scan_flag[SCANB];
__device__ int   g_scan_agg[SCANB];
__device__ int   g_scan_pref[SCANB];
__device__ int2  g_csr[EADJ];                  // (col, fp32 val bits)

// ---------------- helpers ----------------------------------------------------
__device__ __forceinline__ void mma_f16(float* c, const uint32_t* a, const uint32_t* b) {
    asm volatile(
        "mma.sync.aligned.m16n8k16.row.col.f32.f16.f16.f32 "
        "{%0,%1,%2,%3}, {%4,%5,%6,%7}, {%8,%9}, {%0,%1,%2,%3};\n"
        : "+f"(c[0]), "+f"(c[1]), "+f"(c[2]), "+f"(c[3])
        : "r"(a[0]), "r"(a[1]), "r"(a[2]), "r"(a[3]), "r"(b[0]), "r"(b[1]));
}

__device__ __forceinline__ void cp_async16(uint32_t saddr, const void* gptr, int sz) {
    asm volatile("cp.async.ca.shared.global [%0], [%1], 16, %2;\n"
                 :: "r"(saddr), "l"(gptr), "r"(sz));
}
__device__ __forceinline__ void cp_commit() {
    asm volatile("cp.async.commit_group;\n" ::: "memory");
}
__device__ __forceinline__ void cp_wait0() {
    asm volatile("cp.async.wait_group 0;\n" ::: "memory");
}

// ---------------- A pre-convert (BN+ReLU fused for layer 2) ------------------
__global__ __launch_bounds__(256) void conv_a(
    const float* __restrict__ src,
    const float* __restrict__ ab,       // null -> plain convert
    uint2* __restrict__ dst)            // g_ah viewed as uint2 (4 halves)
{
    int gid = blockIdx.x * blockDim.x + threadIdx.x;
    if (gid >= NN * (DD / 4)) return;
    int col = (gid & 31) << 2;
    float4 v = *(const float4*)(src + (size_t)gid * 4);
    if (ab) {
        float4 a4 = *(const float4*)(ab + col);
        float4 b4 = *(const float4*)(ab + DD + col);
        v.x = fmaxf(0.f, fmaf(v.x, a4.x, b4.x));
        v.y = fmaxf(0.f, fmaf(v.y, a4.y, b4.y));
        v.z = fmaxf(0.f, fmaf(v.z, a4.z, b4.z));
        v.w = fmaxf(0.f, fmaf(v.w, a4.w, b4.w));
    }
    __half2 h01 = __floats2half2_rn(v.x, v.y);
    __half2 h23 = __floats2half2_rn(v.z, v.w);
    uint2 pk;
    pk.x = *(uint32_t*)&h01;
    pk.y = *(uint32_t*)&h23;
    dst[gid] = pk;
}

// ---------------- merged fp16 persistent dual GEMM (cp.async A) --------------
// ONE CTA per tile computes BOTH support = A@W (half) and outtmp = A@Wself + b.
// A is pre-converted fp16 in gmem; staged via cp.async (8x16B per thread),
// double buffered, prefetch of tile t+1 overlaps MMA of tile t.
__global__ __launch_bounds__(256) void gemm_hm(
    const __half* __restrict__ Ah_g,
    const float* __restrict__ W,
    const float* __restrict__ Wself,
    const float* __restrict__ bias,
    __half2* __restrict__ suppH,
    float* __restrict__ outtmp)
{
    extern __shared__ __half smh[];
    __half* BhW = smh;                   // 128 x SH
    __half* BhS = smh + DD * SH;         // 128 x SH
    __half* As0 = smh + 2 * DD * SH;     // 128 x SH
    __half* As1 = smh + 3 * DD * SH;     // 128 x SH

    const int tid  = threadIdx.x;
    const int wid  = tid >> 5;
    const int lane = tid & 31;
    const int wy   = wid >> 2;           // 0..1: 64-row slice
    const int wx   = wid & 3;            // 0..3: 32-col slice
    const int g    = lane >> 2;
    const int tig  = lane & 3;

    // ---- stage both B matrices once ----
#pragma unroll
    for (int i = 0; i < 4; i++) {
        int k  = lane;
        int n0 = (wid + i * 8) << 2;
#pragma unroll
        for (int kc = 0; kc < DD; kc += 32) {
            float4 vw = *(const float4*)(W + (size_t)(kc + k) * DD + n0);
            BhW[(n0 + 0) * SH + kc + k] = __float2half_rn(vw.x);
            BhW[(n0 + 1) * SH + kc + k] = __float2half_rn(vw.y);
            BhW[(n0 + 2) * SH + kc + k] = __float2half_rn(vw.z);
            BhW[(n0 + 3) * SH + kc + k] = __float2half_rn(vw.w);
            float4 vs = *(const float4*)(Wself + (size_t)(kc + k) * DD + n0);
            BhS[(n0 + 0) * SH + kc + k] = __float2half_rn(vs.x);
            BhS[(n0 + 1) * SH + kc + k] = __float2half_rn(vs.y);
            BhS[(n0 + 2) * SH + kc + k] = __float2half_rn(vs.z);
            BhS[(n0 + 3) * SH + kc + k] = __float2half_rn(vs.w);
        }
    }

    float2 bb[4];
#pragma unroll
    for (int nt = 0; nt < 4; nt++) {
        int col = wx * 32 + nt * 8 + (tig << 1);
        bb[nt] = *(const float2*)(bias + col);
    }

    const uint32_t sAs0 = (uint32_t)__cvta_generic_to_shared(As0);
    const uint32_t sAs1 = (uint32_t)__cvta_generic_to_shared(As1);
    const int t0 = blockIdx.x;

    // ---- prologue: stage tile 0 via cp.async ----
#pragma unroll
    for (int p = 0; p < 8; p++) {
        int idx = tid + p * 256;             // 0..2047
        int row = idx >> 4;                  // 0..127
        int c16 = idx & 15;                  // 16B chunk
        int gr  = t0 * 128 + row;
        int ok  = (gr < NN) ? 16 : 0;
        const __half* src = Ah_g + ((size_t)(ok ? gr : 0)) * DD + c16 * 8;
        cp_async16(sAs0 + (row * SH + c16 * 8) * 2, src, ok);
    }
    cp_commit();
    cp_wait0();
    __syncthreads();

    uint32_t sCur = sAs0, sNxt = sAs1;
    __half* cur = As0;

    for (int t = t0; t < TILES; t += GEMC) {
        const int tn = t + GEMC;
        // ---- issue cp.async for next tile (overlaps MMA) ----
        if (tn < TILES) {
#pragma unroll
            for (int p = 0; p < 8; p++) {
                int idx = tid + p * 256;
                int row = idx >> 4;
                int c16 = idx & 15;
                int gr  = tn * 128 + row;
                int ok  = (gr < NN) ? 16 : 0;
                const __half* src = Ah_g + ((size_t)(ok ? gr : 0)) * DD + c16 * 8;
                cp_async16(sNxt + (row * SH + c16 * 8) * 2, src, ok);
            }
            cp_commit();
        }

        // ---- compute both matrices for tile t ----
        const uint32_t* Au  = (const uint32_t*)cur;
        const uint32_t* BuW = (const uint32_t*)BhW;
        const uint32_t* BuS = (const uint32_t*)BhS;

        float accW[4][4][4];
        float accS[4][4][4];
#pragma unroll
        for (int mt = 0; mt < 4; mt++)
#pragma unroll
            for (int nt = 0; nt < 4; nt++)
#pragma unroll
                for (int i = 0; i < 4; i++) { accW[mt][nt][i] = 0.f; accS[mt][nt][i] = 0.f; }

#pragma unroll
        for (int ks = 0; ks < 8; ks++) {
            int kb = ks * 8 + tig;
            uint32_t af[4][4];
#pragma unroll
            for (int mt = 0; mt < 4; mt++) {
                int rb = wy * 64 + mt * 16;
                af[mt][0] = Au[(rb + g) * 68 + kb];
                af[mt][1] = Au[(rb + g + 8) * 68 + kb];
                af[mt][2] = Au[(rb + g) * 68 + kb + 4];
                af[mt][3] = Au[(rb + g + 8) * 68 + kb + 4];
            }
            uint32_t bfW[4][2], bfS[4][2];
#pragma unroll
            for (int nt = 0; nt < 4; nt++) {
                int n = wx * 32 + nt * 8 + g;
                bfW[nt][0] = BuW[n * 68 + kb];
                bfW[nt][1] = BuW[n * 68 + kb + 4];
                bfS[nt][0] = BuS[n * 68 + kb];
                bfS[nt][1] = BuS[n * 68 + kb + 4];
            }
#pragma unroll
            for (int mt = 0; mt < 4; mt++)
#pragma unroll
                for (int nt = 0; nt < 4; nt++) {
                    mma_f16(accW[mt][nt], af[mt], bfW[nt]);
                    mma_f16(accS[mt][nt], af[mt], bfS[nt]);
                }
        }

        // ---- epilogue: both outputs ----
        const int m0 = t * 128;
#pragma unroll
        for (int nt = 0; nt < 4; nt++) {
            int col = wx * 32 + nt * 8 + (tig << 1);
#pragma unroll
            for (int mt = 0; mt < 4; mt++) {
                int r0 = m0 + wy * 64 + mt * 16 + g;
                int r1 = r0 + 8;
                if (r0 < NN) {
                    float2 w0 = make_float2(accW[mt][nt][0], accW[mt][nt][1]);
                    suppH[(size_t)r0 * (DD / 2) + (col >> 1)] = __float22half2_rn(w0);
                    float2 s0 = make_float2(accS[mt][nt][0] + bb[nt].x, accS[mt][nt][1] + bb[nt].y);
                    *(float2*)(outtmp + (size_t)r0 * DD + col) = s0;
                }
                if (r1 < NN) {
                    float2 w1 = make_float2(accW[mt][nt][2], accW[mt][nt][3]);
                    suppH[(size_t)r1 * (DD / 2) + (col >> 1)] = __float22half2_rn(w1);
                    float2 s1 = make_float2(accS[mt][nt][2] + bb[nt].x, accS[mt][nt][3] + bb[nt].y);
                    *(float2*)(outtmp + (size_t)r1 * DD + col) = s1;
                }
            }
        }

        cp_wait0();
        __syncthreads();
        uint32_t ts = sCur; sCur = sNxt; sNxt = ts;
        cur = (cur == As0) ? As1 : As0;
    }
}

// ---------------- CSR build ---------------------------------------------------
__global__ __launch_bounds__(256) void histo(const int* __restrict__ rows)
{
    int e = blockIdx.x * blockDim.x + threadIdx.x;
    if (e < EADJ) atomicAdd(&g_counts[rows[e]], 1);
}

__global__ __launch_bounds__(256) void scan_lookback()
{
    __shared__ int ws[8];
    __shared__ int s_prefix;
    const int bid = blockIdx.x;
    const int tid = threadIdx.x, lane = tid & 31, w = tid >> 5;
    int i = bid * 256 + tid;
    int v = (i < NN) ? g_counts[i] : 0;
    int inc = v;
#pragma unroll
    for (int o = 1; o < 32; o <<= 1) {
        int n = __shfl_up_sync(0xFFFFFFFFu, inc, o);
        if (lane >= o) inc += n;
    }
    if (lane == 31) ws[w] = inc;
    __syncthreads();
    if (w == 0 && lane < 8) {
        int s = ws[lane];
#pragma unroll
        for (int o = 1; o < 8; o <<= 1) {
            int n = __shfl_up_sync(0xFFu, s, o);
            if (lane >= o) s += n;
        }
        ws[lane] = s;
    }
    __syncthreads();
    int local_excl = (w ? ws[w - 1] : 0) + inc - v;
    int total = ws[7];

    if (tid == 0) {
        if (bid == 0) {
            g_scan_pref[0] = total;
            __threadfence();
            g_scan_flag[0] = 2;
            s_prefix = 0;
        } else {
            g_scan_agg[bid] = total;
            __threadfence();
            g_scan_flag[bid] = 1;
            int pref = 0;
            for (int j = bid - 1; j >= 0; j--) {
                int f;
                do { f = *(volatile int*)&g_scan_flag[j]; } while (f == 0);
                __threadfence();
                if (f == 2) { pref += *(volatile int*)&g_scan_pref[j]; break; }
                pref += *(volatile int*)&g_scan_agg[j];
            }
            g_scan_pref[bid] = pref + total;
            __threadfence();
            g_scan_flag[bid] = 2;
            s_prefix = pref;
        }
    }
    __syncthreads();
    int excl = s_prefix + local_excl;
    if (i < NN) { g_rowstart[i] = excl; g_cursor[i] = excl; }
    if (i == 0) g_rowstart[NN] = EADJ;
}

__global__ __launch_bounds__(256) void scatter_csr(
    const int* __restrict__ rows, const int* __restrict__ cols,
    const float* __restrict__ vals)
{
    int e = blockIdx.x * blockDim.x + threadIdx.x;
    if (e >= EADJ) return;
    int p = atomicAdd(&g_cursor[rows[e]], 1);
    g_csr[p] = make_int2(cols[e], __float_as_int(vals[e]));
}

// ---------------- CSR SpMM (half gather, 1 row/warp) + fused BN stats --------
__global__ __launch_bounds__(256) void spmm_csr(
    const __half2* __restrict__ S2, float* __restrict__ Out,
    float* __restrict__ statpart)
{
    int lane = threadIdx.x & 31;
    int w    = threadIdx.x >> 5;
    int cg   = lane << 2;
    const int h2off = lane << 1;
    int row  = blockIdx.x * 8 + w;

    float4 s = make_float4(0.f, 0.f, 0.f, 0.f);
    float4 q = make_float4(0.f, 0.f, 0.f, 0.f);

    if (row < NN) {
        int e0 = g_rowstart[row];
        int e1 = g_rowstart[row + 1];
        float4 acc = make_float4(0.f, 0.f, 0.f, 0.f);
        int i = e0;
        for (; i + 4 <= e1; i += 4) {
            int2 cv0 = g_csr[i + 0];
            int2 cv1 = g_csr[i + 1];
            int2 cv2 = g_csr[i + 2];
            int2 cv3 = g_csr[i + 3];
            uint2 r0 = *(const uint2*)(S2 + (size_t)cv0.x * (DD / 2) + h2off);
            uint2 r1 = *(const uint2*)(S2 + (size_t)cv1.x * (DD / 2) + h2off);
            uint2 r2 = *(const uint2*)(S2 + (size_t)cv2.x * (DD / 2) + h2off);
            uint2 r3 = *(const uint2*)(S2 + (size_t)cv3.x * (DD / 2) + h2off);
            float v0 = __int_as_float(cv0.y), v1 = __int_as_float(cv1.y);
            float v2 = __int_as_float(cv2.y), v3 = __int_as_float(cv3.y);
            float2 a0 = __half22float2(*(__half2*)&r0.x), b0 = __half22float2(*(__half2*)&r0.y);
            float2 a1 = __half22float2(*(__half2*)&r1.x), b1 = __half22float2(*(__half2*)&r1.y);
            float2 a2 = __half22float2(*(__half2*)&r2.x), b2 = __half22float2(*(__half2*)&r2.y);
            float2 a3 = __half22float2(*(__half2*)&r3.x), b3 = __half22float2(*(__half2*)&r3.y);
            acc.x += v0 * a0.x + v1 * a1.x + v2 * a2.x + v3 * a3.x;
            acc.y += v0 * a0.y + v1 * a1.y + v2 * a2.y + v3 * a3.y;
            acc.z += v0 * b0.x + v1 * b1.x + v2 * b2.x + v3 * b3.x;
            acc.w += v0 * b0.y + v1 * b1.y + v2 * b2.y + v3 * b3.y;
        }
        for (; i < e1; i++) {
            int2 cv = g_csr[i];
            float vv = __int_as_float(cv.y);
            uint2 rr = *(const uint2*)(S2 + (size_t)cv.x * (DD / 2) + h2off);
            float2 aa = __half22float2(*(__half2*)&rr.x);
            float2 bbv = __half22float2(*(__half2*)&rr.y);
            acc.x += vv * aa.x; acc.y += vv * aa.y;
            acc.z += vv * bbv.x; acc.w += vv * bbv.y;
        }
        float4* p = (float4*)(Out + (size_t)row * DD + cg);
        float4 t = *p;
        t.x += acc.x; t.y += acc.y; t.z += acc.z; t.w += acc.w;
        *p = t;
        s = t;
        q.x = t.x * t.x; q.y = t.y * t.y;
        q.z = t.z * t.z; q.w = t.w * t.w;
    }

    __shared__ float4 ss[8][32];
    __shared__ float4 qq[8][32];
    ss[w][lane] = s;
    qq[w][lane] = q;
    __syncthreads();
    if (w == 0) {
#pragma unroll
        for (int k = 1; k < 8; k++) {
            float4 a = ss[k][lane], b = qq[k][lane];
            s.x += a.x; s.y += a.y; s.z += a.z; s.w += a.w;
            q.x += b.x; q.y += b.y; q.z += b.z; q.w += b.w;
        }
        float* base = statpart + (size_t)(blockIdx.x & (NCOPY - 1)) * 2 * DD;
        atomicAdd((float4*)(base + cg), s);
        atomicAdd((float4*)(base + DD + cg), q);
    }
}

// fold NCOPY partials -> BN scale/shift
__global__ __launch_bounds__(128) void reduce_stats(
    const float* __restrict__ statpart,
    const float* __restrict__ gm, const float* __restrict__ be,
    float* __restrict__ ab)
{
    int col = threadIdx.x;
    float s = 0.f, q = 0.f;
#pragma unroll
    for (int c = 0; c < NCOPY; c++) {
        s += statpart[c * 2 * DD + col];
        q += statpart[c * 2 * DD + DD + col];
    }
    const float invN = 1.0f / (float)NN;
    float m   = s * invN;
    float var = q * invN - m * m;
    float a   = gm[col] * rsqrtf(var + BNEPS);
    ab[col]      = a;
    ab[DD + col] = be[col] - m * a;
}

// ---------------- node scores (BN layer2 fused) -------------------------------
__global__ __launch_bounds__(256) void node_scores(
    const float* __restrict__ T2,
    const float* __restrict__ ab,
    const float* __restrict__ X,
    const float* __restrict__ Wc)
{
    int warp = (blockIdx.x * blockDim.x + threadIdx.x) >> 5;
    int lane = threadIdx.x & 31;
    if (warp >= NN) return;
    int cg = lane << 2;
    size_t off = (size_t)warp * DD + cg;
    float4 t = *(const float4*)(T2 + off);
    float4 x = *(const float4*)(X + off);
    float4 a4 = *(const float4*)(ab + cg);
    float4 b4 = *(const float4*)(ab + DD + cg);
    float h0 = fmaxf(0.f, fmaf(t.x, a4.x, b4.x)) + x.x;
    float h1 = fmaxf(0.f, fmaf(t.y, a4.y, b4.y)) + x.y;
    float h2 = fmaxf(0.f, fmaf(t.z, a4.z, b4.z)) + x.z;
    float h3 = fmaxf(0.f, fmaf(t.w, a4.w, b4.w)) + x.w;
    float4 w1 = *(const float4*)(Wc + cg);
    float4 w2 = *(const float4*)(Wc + DD + cg);
    float s1 = h0 * w1.x + h1 * w1.y + h2 * w1.z + h3 * w1.w;
    float s2 = h0 * w2.x + h1 * w2.y + h2 * w2.z + h3 * w2.w;
#pragma unroll
    for (int o = 16; o; o >>= 1) {
        s1 += __shfl_xor_sync(0xFFFFFFFFu, s1, o);
        s2 += __shfl_xor_sync(0xFFFFFFFFu, s2, o);
    }
    if (lane == 0) {
        g_s1[warp] = s1;
        g_s2[warp] = s2;
    }
}

// ---------------- edge prediction ---------------------------------------------
__global__ __launch_bounds__(256) void edge_pred(
    const int* __restrict__ ei,
    const float* __restrict__ bc,
    float* __restrict__ out)
{
    int e = blockIdx.x * blockDim.x + threadIdx.x;
    if (e >= EPRED) return;
    float z = g_s1[ei[e]] + g_s2[ei[e + EPRED]] + bc[0];
    out[e] = 1.0f / (1.0f + expf(-z));
}

// ---------------- launch ------------------------------------------------------
extern "C" void kernel_launch(void* const* d_in, const int* in_sizes, int n_in,
                              void* d_out, int out_size)
{
    const float* x       = (const float*)d_in[0];
    const int*   adj_row = (const int*)d_in[1];
    const int*   adj_col = (const int*)d_in[2];
    const float* adj_val = (const float*)d_in[3];
    const int*   eidx    = (const int*)d_in[4];
    const float* W       = (const float*)d_in[5];
    const float* Wself   = (const float*)d_in[6];
    const float* b       = (const float*)d_in[7];
    const float* gamma   = (const float*)d_in[8];
    const float* beta    = (const float*)d_in[9];
    const float* Wc      = (const float*)d_in[10];
    const float* bc      = (const float*)d_in[11];
    float* out           = (float*)d_out;

    __half2* suppH; __half* ah; float *tmp, *tmp2, *statpart, *bnab;
    int *counts, *flags;
    cudaGetSymbolAddress((void**)&suppH,    g_supp_h);
    cudaGetSymbolAddress((void**)&ah,       g_ah);
    cudaGetSymbolAddress((void**)&tmp,      g_tmp);
    cudaGetSymbolAddress((void**)&tmp2,     g_tmp2);
    cudaGetSymbolAddress((void**)&statpart, g_statpart);
    cudaGetSymbolAddress((void**)&bnab,     g_bnab);
    cudaGetSymbolAddress((void**)&counts,   g_counts);
    cudaGetSymbolAddress((void**)&flags,    g_scan_flag);

    const int gemm_smem = 4 * DD * SH * (int)sizeof(__half);   // 2 B + 2 A bufs
    cudaFuncSetAttribute(gemm_hm,
                         cudaFuncAttributeMaxDynamicSharedMemorySize, gemm_smem);

    const int eb = (EADJ + 255) / 256;
    const int spmm_blocks = (NN + 7) / 8;
    const int conv_blocks = (NN * (DD / 4) + 255) / 256;

    cudaMemsetAsync(counts, 0, NN * sizeof(int));
    cudaMemsetAsync(flags, 0, SCANB * sizeof(int));
    cudaMemsetAsync(statpart, 0, 2 * NCOPY * 2 * DD * sizeof(float));

    // CSR build
    histo<<<eb, 256>>>(adj_row);
    scan_lookback<<<SCANB, 256>>>();
    scatter_csr<<<eb, 256>>>(adj_row, adj_col, adj_val);

    // layer 1: conv(x) -> A_h; gemm -> suppH, tmp
    conv_a<<<conv_blocks, 256>>>(x, nullptr, (uint2*)ah);
    gemm_hm<<<GEMC, 256, gemm_smem>>>(ah, W, Wself, b, suppH, tmp);
    spmm_csr<<<spmm_blocks, 256>>>(suppH, tmp, statpart);
    reduce_stats<<<1, 128>>>(statpart, gamma, beta, bnab);

    // layer 2: conv(relu(bn(tmp))) -> A_h; gemm -> suppH, tmp2
    conv_a<<<conv_blocks, 256>>>(tmp, bnab, (uint2*)ah);
    gemm_hm<<<GEMC, 256, gemm_smem>>>(ah, W + DD * DD, Wself + DD * DD,
                                      b + DD, suppH, tmp2);
    spmm_csr<<<spmm_blocks, 256>>>(suppH, tmp2, statpart + NCOPY * 2 * DD);
    reduce_stats<<<1, 128>>>(statpart + NCOPY * 2 * DD, gamma + DD, beta + DD,
                             bnab + 2 * DD);

    node_scores<<<(NN * 32 + 255) / 256, 256>>>(tmp2, bnab + 2 * DD, x, Wc);
    edge_pred<<<(EPRED + 255) / 256, 256>>>(eidx, bc, out);
}